// round 2
// baseline (speedup 1.0000x reference)
#include <cuda_runtime.h>
#include <cstdint>

#define BATCH 4
#define KTOP 6000
#define OUTN 1000
#define NBINS 65536
#define CAP 6080
#define WORDS 94            // ceil(6000/64)
#define NMS_THR 0.7f

// ---------------- scratch (device globals; no allocations) ----------------
__device__ unsigned int       g_hist[BATCH * NBINS];          // 1 MB
__device__ unsigned int       g_thresh[BATCH];
__device__ unsigned int       g_candcnt[BATCH];
__device__ unsigned long long g_cand[BATCH * CAP];            // 190 KB
__device__ float4             g_boxes[BATCH * KTOP];          // 384 KB
__device__ unsigned long long g_mask[(size_t)BATCH * KTOP * WORDS]; // 18 MB
__device__ int                g_keep[BATCH * OUTN];
__device__ int                g_kept[BATCH];

// ---------------- K0: zero histogram + counters ----------------
__global__ void k_zero() {
    int t = blockIdx.x * blockDim.x + threadIdx.x;
    int stride = gridDim.x * blockDim.x;
    for (int i = t; i < BATCH * NBINS; i += stride) g_hist[i] = 0;
    if (t < BATCH) g_candcnt[t] = 0;
}

// ---------------- K1: 65536-bin histogram of fg scores ----------------
__global__ void k_hist(const float* __restrict__ scores, int N) {
    int b = blockIdx.y;
    const float* sp = scores + (size_t)b * N * 2;
    for (int n = blockIdx.x * blockDim.x + threadIdx.x; n < N; n += gridDim.x * blockDim.x) {
        float s = fmaxf(sp[2 * n + 1], 0.0f);
        unsigned bin = min((unsigned)(s * 65536.0f), 65535u);
        atomicAdd(&g_hist[b * NBINS + bin], 1u);
    }
}

// ---------------- K2: find threshold bin (suffix count >= KTOP) ----------------
__global__ void k_select() {
    int b = blockIdx.x, t = threadIdx.x;
    __shared__ unsigned suf[1024];
    const unsigned* h = &g_hist[b * NBINS];
    unsigned s = 0;
#pragma unroll 8
    for (int k = 0; k < 64; k++) s += h[t * 64 + k];
    suf[t] = s;
    __syncthreads();
    for (int off = 1; off < 1024; off <<= 1) {
        unsigned add = (t + off < 1024) ? suf[t + off] : 0u;
        __syncthreads();
        suf[t] += add;
        __syncthreads();
    }
    if (t == 0) {
        int c = 0;
        for (int i = 1023; i >= 0; i--) {
            if (suf[i] >= (unsigned)KTOP) { c = i; break; }
        }
        unsigned run = (c < 1023) ? suf[c + 1] : 0u;
        unsigned T = (unsigned)(c * 64);
        for (int bin = c * 64 + 63; bin >= c * 64; bin--) {
            run += h[bin];
            if (run >= (unsigned)KTOP) { T = (unsigned)bin; break; }
        }
        g_thresh[b] = T;
    }
}

// ---------------- K3: gather candidates (composite key) ----------------
__global__ void k_gather(const float* __restrict__ scores, int N) {
    int b = blockIdx.y;
    const unsigned T = g_thresh[b];
    const float* sp = scores + (size_t)b * N * 2;
    for (int n = blockIdx.x * blockDim.x + threadIdx.x; n < N; n += gridDim.x * blockDim.x) {
        float s = sp[2 * n + 1];
        float sc = fmaxf(s, 0.0f);
        unsigned bin = min((unsigned)(sc * 65536.0f), 65535u);
        if (bin >= T) {
            unsigned pos = atomicAdd(&g_candcnt[b], 1u);
            if (pos < CAP) {
                unsigned long long key =
                    ((unsigned long long)__float_as_uint(s) << 32) | (unsigned)(~(unsigned)n);
                g_cand[b * CAP + pos] = key;
            }
        }
    }
}

// ---------------- K4: counting-rank sort + box decode + clip ----------------
__global__ void k_rank(const float* __restrict__ deltas, const float* __restrict__ anchors, int N) {
    int b = blockIdx.y;
    __shared__ __align__(16) unsigned long long sh[CAP];
    int M = (int)min(g_candcnt[b], (unsigned)CAP);
    for (int j = threadIdx.x; j < M; j += blockDim.x) sh[j] = g_cand[b * CAP + j];
    __syncthreads();

    int i = blockIdx.x * blockDim.x + threadIdx.x;
    if (i >= M) return;
    unsigned long long mykey = sh[i];
    int rank = 0;
    const ulonglong2* sh2 = (const ulonglong2*)sh;
    int M2 = M >> 1;
    int j = 0;
#pragma unroll 4
    for (; j < M2; j++) {
        ulonglong2 v = sh2[j];
        rank += (v.x > mykey) + (v.y > mykey);
    }
    if (M & 1) rank += (sh[M - 1] > mykey);
    if (rank >= KTOP) return;

    unsigned idx = ~(unsigned)(mykey & 0xFFFFFFFFull);
    float4 a = ((const float4*)anchors)[(size_t)b * N + idx];
    float4 d = ((const float4*)deltas)[(size_t)b * N + idx];
    float dx = d.x * 0.1f, dy = d.y * 0.1f, dw = d.z * 0.2f, dh = d.w * 0.2f;
    float w = a.z - a.x, h = a.w - a.y;
    float cx = a.x + 0.5f * w;  cx = cx + dx * w;
    float cy = a.y + 0.5f * h;  cy = cy + dy * h;
    w = w * expf(dw);
    h = h * expf(dh);
    float x1 = cx - 0.5f * w, y1 = cy - 0.5f * h;
    float x2 = cx + 0.5f * w, y2 = cy + 0.5f * h;
    x1 = fminf(fmaxf(x1, 0.0f), 1.0f);
    y1 = fminf(fmaxf(y1, 0.0f), 1.0f);
    x2 = fminf(fmaxf(x2, 0.0f), 1.0f);
    y2 = fminf(fmaxf(y2, 0.0f), 1.0f);
    g_boxes[b * KTOP + rank] = make_float4(x1, y1, x2, y2);
}

// ---------------- K5: triangular IoU suppression bitmask ----------------
__global__ void k_mask() {
    int rb = blockIdx.x, cb = blockIdx.y, b = blockIdx.z;
    int tid = threadIdx.x;
    int i = rb * 64 + tid;
    if (cb < rb) {  // lower-triangle rows must still be zeroed
        if (i < KTOP) g_mask[((size_t)b * KTOP + i) * WORDS + cb] = 0ull;
        return;
    }
    __shared__ float4 cbx[64];
    __shared__ float  car[64];
    int j0 = cb * 64;
    int jj = j0 + tid;
    float4 bj = (jj < KTOP) ? g_boxes[b * KTOP + jj] : make_float4(0, 0, 0, 0);
    cbx[tid] = bj;
    car[tid] = (bj.z - bj.x) * (bj.w - bj.y);
    __syncthreads();
    if (i >= KTOP) return;
    float4 bi = g_boxes[b * KTOP + i];
    float ai = (bi.z - bi.x) * (bi.w - bi.y);
    unsigned long long bits = 0;
#pragma unroll 8
    for (int k = 0; k < 64; k++) {
        int jg = j0 + k;
        if (jg > i && jg < KTOP) {
            float4 bb = cbx[k];
            float lx = fmaxf(bi.x, bb.x), ly = fmaxf(bi.y, bb.y);
            float rx = fminf(bi.z, bb.z), ry = fminf(bi.w, bb.w);
            float iw = fmaxf(rx - lx, 0.0f), ih = fmaxf(ry - ly, 0.0f);
            float inter = iw * ih;
            float iou = inter / (ai + car[k] - inter + 1e-12f);
            if (iou > NMS_THR) bits |= (1ull << k);
        }
    }
    g_mask[((size_t)b * KTOP + i) * WORDS + cb] = bits;
}

// ---------------- K6: serial greedy scan (1 warp / batch) ----------------
__device__ __forceinline__ void issue_row(const unsigned long long* src_row,
                                          unsigned dst_smem, int lane) {
    // 94 words = 752 B = 47 x 16B chunks. Lane l: chunk l; lanes 0..14 also chunk 32+l.
    asm volatile("cp.async.ca.shared.global [%0], [%1], 16;\n"
                 :: "r"(dst_smem + lane * 16),
                    "l"((const char*)src_row + lane * 16));
    if (lane < 15)
        asm volatile("cp.async.ca.shared.global [%0], [%1], 16;\n"
                     :: "r"(dst_smem + 512 + lane * 16),
                        "l"((const char*)src_row + 512 + lane * 16));
}

__global__ void k_scan() {
    int b = blockIdx.x;
    int lane = threadIdx.x;  // blockDim = 32
    __shared__ __align__(16) unsigned long long ring[8][WORDS];
    __shared__ unsigned long long removed[WORDS];
    removed[lane] = 0; removed[lane + 32] = 0;
    if (lane < WORDS - 64) removed[lane + 64] = 0;
    __syncwarp();

    const unsigned long long* maskb = g_mask + (size_t)b * KTOP * WORDS;
    unsigned ring_base = (unsigned)__cvta_generic_to_shared(&ring[0][0]);

    for (int p = 0; p < 7; p++) {
        issue_row(maskb + (size_t)p * WORDS, ring_base + (p & 7) * (WORDS * 8), lane);
        asm volatile("cp.async.commit_group;\n");
    }

    unsigned long long cur = 0;
    int kept = 0;
    for (int i = 0; i < KTOP; i++) {
        int r = i + 7;
        if (r < KTOP)
            issue_row(maskb + (size_t)r * WORDS, ring_base + (r & 7) * (WORDS * 8), lane);
        asm volatile("cp.async.commit_group;\n");
        asm volatile("cp.async.wait_group 7;\n");

        int w = i >> 6;
        if ((i & 63) == 0 && i) { __syncwarp(); cur = removed[w]; }

        if (!((cur >> (i & 63)) & 1ull)) {
            if (lane == 0) g_keep[b * OUTN + kept] = i;
            kept++;
            if (kept == OUTN) break;
            __syncwarp();  // make cp.async-filled ring slot visible to all lanes
            const unsigned long long* row = ring[i & 7];
            cur |= row[w];
            removed[lane]      |= row[lane];
            removed[lane + 32] |= row[lane + 32];
            if (lane < WORDS - 64) removed[lane + 64] |= row[lane + 64];
        }
    }
    asm volatile("cp.async.wait_group 0;\n");
    __syncwarp();
    if (lane == 0) g_kept[b] = kept;
}

// ---------------- K7: write output (zero-padded) ----------------
__global__ void k_out(float4* __restrict__ out) {
    int t = blockIdx.x * blockDim.x + threadIdx.x;
    if (t >= BATCH * OUTN) return;
    int b = t / OUTN, r = t % OUTN;
    float4 v = make_float4(0, 0, 0, 0);
    if (r < g_kept[b]) v = g_boxes[b * KTOP + g_keep[b * OUTN + r]];
    out[t] = v;
}

// ---------------- launch ----------------
extern "C" void kernel_launch(void* const* d_in, const int* in_sizes, int n_in,
                              void* d_out, int out_size) {
    const float* scores  = (const float*)d_in[0];
    const float* deltas  = (const float*)d_in[1];
    const float* anchors = (const float*)d_in[2];
    int N = in_sizes[0] / (BATCH * 2);

    k_zero<<<256, 256>>>();
    k_hist<<<dim3(512, BATCH), 256>>>(scores, N);
    k_select<<<BATCH, 1024>>>();
    k_gather<<<dim3(512, BATCH), 256>>>(scores, N);
    k_rank<<<dim3(12, BATCH), 512>>>(deltas, anchors, N);
    k_mask<<<dim3(WORDS, WORDS, BATCH), 64>>>();
    k_scan<<<BATCH, 32>>>();
    k_out<<<16, 256>>>((float4*)d_out);
}

// round 5
// speedup vs baseline: 1.6916x; 1.6916x over previous
#include <cuda_runtime.h>
#include <cstdint>

#define BATCH 4
#define KTOP 6000
#define OUTN 1000
#define NBINS 65536
#define CAP 6080
#define WORDS 94            // ceil(6000/64)  (fallback path)
#define CLIM 2048           // fast-path NMS window
#define WORDS_C 32          // CLIM/64
#define NMS_THR 0.7f

// ---------------- scratch (device globals; no allocations) ----------------
__device__ unsigned int       g_hist[BATCH * NBINS];                  // 1 MB
__device__ unsigned int       g_thresh[BATCH];
__device__ unsigned int       g_candcnt[BATCH];
__device__ unsigned long long g_cand[BATCH * CAP];
__device__ float4             g_boxes[BATCH * KTOP];
__device__ unsigned long long g_maskC[(size_t)BATCH * CLIM * WORDS_C]; // 2 MB
__device__ unsigned long long g_mask[(size_t)BATCH * KTOP * WORDS];    // 18 MB (fallback only)
__device__ int                g_keep[BATCH * OUTN];
__device__ int                g_kept[BATCH];
__device__ int                g_need;   // 1 => fast-path window insufficient

// ---------------- K0: zero histogram + counters + flag ----------------
__global__ void k_zero() {
    int t = blockIdx.x * blockDim.x + threadIdx.x;
    int stride = gridDim.x * blockDim.x;
    for (int i = t; i < BATCH * NBINS; i += stride) g_hist[i] = 0;
    if (t < BATCH) g_candcnt[t] = 0;
    if (t == 0) g_need = 0;
}

// ---------------- K1: 65536-bin histogram (float4 loads) ----------------
__global__ void k_hist(const float* __restrict__ scores, int N) {
    int b = blockIdx.y;
    int N4 = N >> 1;  // float4 = 2 (bg,fg) pairs
    const float4* p = (const float4*)(scores + (size_t)b * N * 2);
    unsigned* h = g_hist + b * NBINS;
#pragma unroll 2
    for (int i = blockIdx.x * blockDim.x + threadIdx.x; i < N4; i += gridDim.x * blockDim.x) {
        float4 v = p[i];
        unsigned b0 = min((unsigned)(fmaxf(v.y, 0.0f) * 65536.0f), 65535u);
        unsigned b1 = min((unsigned)(fmaxf(v.w, 0.0f) * 65536.0f), 65535u);
        atomicAdd(&h[b0], 1u);
        atomicAdd(&h[b1], 1u);
    }
}

// ---------------- K2: find threshold bin (suffix count >= KTOP) ----------------
__global__ void k_select() {
    int b = blockIdx.x, t = threadIdx.x;
    __shared__ unsigned suf[1024];
    const unsigned* h = &g_hist[b * NBINS];
    unsigned s = 0;
#pragma unroll 8
    for (int k = 0; k < 64; k++) s += h[t * 64 + k];
    suf[t] = s;
    __syncthreads();
    for (int off = 1; off < 1024; off <<= 1) {
        unsigned add = (t + off < 1024) ? suf[t + off] : 0u;
        __syncthreads();
        suf[t] += add;
        __syncthreads();
    }
    if (t == 0) {
        int c = 0;
        for (int i = 1023; i >= 0; i--) {
            if (suf[i] >= (unsigned)KTOP) { c = i; break; }
        }
        unsigned run = (c < 1023) ? suf[c + 1] : 0u;
        unsigned T = (unsigned)(c * 64);
        for (int bin = c * 64 + 63; bin >= c * 64; bin--) {
            run += h[bin];
            if (run >= (unsigned)KTOP) { T = (unsigned)bin; break; }
        }
        g_thresh[b] = T;
    }
}

// ---------------- K3: gather candidates (float4 loads, composite key) ----------------
__global__ void k_gather(const float* __restrict__ scores, int N) {
    int b = blockIdx.y;
    const unsigned T = g_thresh[b];
    int N4 = N >> 1;
    const float4* p = (const float4*)(scores + (size_t)b * N * 2);
#pragma unroll 2
    for (int i = blockIdx.x * blockDim.x + threadIdx.x; i < N4; i += gridDim.x * blockDim.x) {
        float4 v = p[i];
        float s0 = v.y, s1 = v.w;
        unsigned b0 = min((unsigned)(fmaxf(s0, 0.0f) * 65536.0f), 65535u);
        unsigned b1 = min((unsigned)(fmaxf(s1, 0.0f) * 65536.0f), 65535u);
        if (b0 >= T) {
            unsigned pos = atomicAdd(&g_candcnt[b], 1u);
            if (pos < CAP)
                g_cand[b * CAP + pos] =
                    ((unsigned long long)__float_as_uint(s0) << 32) | (unsigned)(~(unsigned)(2 * i));
        }
        if (b1 >= T) {
            unsigned pos = atomicAdd(&g_candcnt[b], 1u);
            if (pos < CAP)
                g_cand[b * CAP + pos] =
                    ((unsigned long long)__float_as_uint(s1) << 32) | (unsigned)(~(unsigned)(2 * i + 1));
        }
    }
}

// ---------------- K4: counting-rank sort + box decode + clip ----------------
__global__ void k_rank(const float* __restrict__ deltas, const float* __restrict__ anchors, int N) {
    int b = blockIdx.y;
    __shared__ __align__(16) unsigned long long sh[CAP];
    int M = (int)min(g_candcnt[b], (unsigned)CAP);
    for (int j = threadIdx.x; j < M; j += blockDim.x) sh[j] = g_cand[b * CAP + j];
    __syncthreads();

    int i = blockIdx.x * blockDim.x + threadIdx.x;
    if (i >= M) return;
    unsigned long long mykey = sh[i];
    int rank = 0;
    const ulonglong2* sh2 = (const ulonglong2*)sh;
    int M2 = M >> 1;
#pragma unroll 4
    for (int j = 0; j < M2; j++) {
        ulonglong2 v = sh2[j];
        rank += (v.x > mykey) + (v.y > mykey);
    }
    if (M & 1) rank += (sh[M - 1] > mykey);
    if (rank >= KTOP) return;

    unsigned idx = ~(unsigned)(mykey & 0xFFFFFFFFull);
    float4 a = ((const float4*)anchors)[(size_t)b * N + idx];
    float4 d = ((const float4*)deltas)[(size_t)b * N + idx];
    float dx = d.x * 0.1f, dy = d.y * 0.1f, dw = d.z * 0.2f, dh = d.w * 0.2f;
    float w = a.z - a.x, h = a.w - a.y;
    float cx = a.x + 0.5f * w;  cx = cx + dx * w;
    float cy = a.y + 0.5f * h;  cy = cy + dy * h;
    w = w * expf(dw);
    h = h * expf(dh);
    float x1 = cx - 0.5f * w, y1 = cy - 0.5f * h;
    float x2 = cx + 0.5f * w, y2 = cy + 0.5f * h;
    x1 = fminf(fmaxf(x1, 0.0f), 1.0f);
    y1 = fminf(fmaxf(y1, 0.0f), 1.0f);
    x2 = fminf(fmaxf(x2, 0.0f), 1.0f);
    y2 = fminf(fmaxf(y2, 0.0f), 1.0f);
    g_boxes[b * KTOP + rank] = make_float4(x1, y1, x2, y2);
}

// ---------------- IoU test (division-free) ----------------
__device__ __forceinline__ bool iou_gt(float4 bi, float ai, float4 bb, float ab) {
    float lx = fmaxf(bi.x, bb.x), ly = fmaxf(bi.y, bb.y);
    float rx = fminf(bi.z, bb.z), ry = fminf(bi.w, bb.w);
    float iw = fmaxf(rx - lx, 0.0f), ih = fmaxf(ry - ly, 0.0f);
    float inter = iw * ih;
    // inter/(ai+ab-inter) > 0.7  <=>  1.7*inter > 0.7*(ai+ab)
    return (1.0f + NMS_THR) * inter > NMS_THR * (ai + ab);
}

// ---------------- K5: IoU bitmask, 2048x2048 window ----------------
__global__ void k_maskC() {
    int rb = blockIdx.x, cb = blockIdx.y, b = blockIdx.z;
    int tid = threadIdx.x;
    int i = rb * 64 + tid;
    size_t rowbase = ((size_t)b * CLIM + i) * WORDS_C;
    if (cb < rb) { g_maskC[rowbase + cb] = 0ull; return; }
    __shared__ float4 cbx[64];
    __shared__ float  car[64];
    int j0 = cb * 64;
    float4 bj = g_boxes[b * KTOP + j0 + tid];
    cbx[tid] = bj;
    car[tid] = (bj.z - bj.x) * (bj.w - bj.y);
    __syncthreads();
    float4 bi = g_boxes[b * KTOP + i];
    float ai = (bi.z - bi.x) * (bi.w - bi.y);
    unsigned long long bits = 0;
    if (cb == rb) {
        for (int k = tid + 1; k < 64; k++)
            if (iou_gt(bi, ai, cbx[k], car[k])) bits |= (1ull << k);
    } else {
#pragma unroll 8
        for (int k = 0; k < 64; k++)
            if (iou_gt(bi, ai, cbx[k], car[k])) bits |= (1ull << k);
    }
    g_maskC[rowbase + cb] = bits;
}

// ---------------- K6: serial greedy scan, register-resident removed ----------------
__global__ void k_scanC() {
    int b = blockIdx.x;
    int lane = threadIdx.x;  // blockDim = 32
    __shared__ __align__(16) unsigned long long ring[8][WORDS_C];
    const unsigned long long* maskb = g_maskC + (size_t)b * CLIM * WORDS_C;
    unsigned ring_base = (unsigned)__cvta_generic_to_shared(&ring[0][0]);

    // prefetch rows 0..6 (each lane<16 copies its own 16B chunk)
    for (int p = 0; p < 7; p++) {
        if (lane < 16)
            asm volatile("cp.async.ca.shared.global [%0], [%1], 16;\n"
                         :: "r"(ring_base + (p & 7) * 256 + lane * 16),
                            "l"((const char*)(maskb + (size_t)p * WORDS_C) + lane * 16));
        asm volatile("cp.async.commit_group;\n");
    }

    unsigned long long rem0 = 0, rem1 = 0, cur = 0;  // lane<16 owns words 2*lane, 2*lane+1
    int kept = 0;
    bool fail = true;
    for (int i = 0; i < CLIM; i++) {
        int r = i + 7;
        if (lane < 16 && r < CLIM)
            asm volatile("cp.async.ca.shared.global [%0], [%1], 16;\n"
                         :: "r"(ring_base + (r & 7) * 256 + lane * 16),
                            "l"((const char*)(maskb + (size_t)r * WORDS_C) + lane * 16));
        asm volatile("cp.async.commit_group;\n");
        asm volatile("cp.async.wait_group 7;\n");

        if (i && (i & 63) == 0) {
            int w = i >> 6;
            unsigned long long v = (w & 1) ? rem1 : rem0;
            cur = __shfl_sync(0xffffffffu, v, w >> 1);
        }
        if (!((cur >> (i & 63)) & 1ull)) {
            if (lane == 0) g_keep[b * OUTN + kept] = i;
            if (++kept == OUTN) { fail = false; break; }
            if (lane < 16) {
                // each lane reads only the bytes IT copied -> no syncwarp needed
                ulonglong2 t = ((const ulonglong2*)&ring[i & 7][0])[lane];
                rem0 |= t.x;
                rem1 |= t.y;
            }
            int w = i >> 6;
            unsigned long long v = (w & 1) ? rem1 : rem0;
            cur = __shfl_sync(0xffffffffu, v, w >> 1);
        }
    }
    asm volatile("cp.async.wait_group 0;\n");
    if (lane == 0) {
        g_kept[b] = kept;
        if (fail) g_need = 1;   // window exhausted without 1000 keeps -> fallback
    }
}

// ---------------- Fallback A: full 6000x6000 mask (persistent, gated) ----------------
__global__ void k_mask_full() {
    if (g_need == 0) return;
    int tid = threadIdx.x;
    __shared__ float4 cbx[64];
    __shared__ float  car[64];
    for (int t = blockIdx.x; t < BATCH * WORDS * WORDS; t += gridDim.x) {
        int b  = t / (WORDS * WORDS);
        int r  = t % (WORDS * WORDS);
        int rb = r / WORDS, cb = r % WORDS;
        int i  = rb * 64 + tid;
        size_t rowbase = ((size_t)b * KTOP + i) * WORDS;
        __syncthreads();
        if (cb < rb) {
            if (i < KTOP) g_mask[rowbase + cb] = 0ull;
            continue;
        }
        int j0 = cb * 64;
        int jj = j0 + tid;
        float4 bj = (jj < KTOP) ? g_boxes[b * KTOP + jj] : make_float4(0, 0, 0, 0);
        cbx[tid] = bj;
        car[tid] = (bj.z - bj.x) * (bj.w - bj.y);
        __syncthreads();
        if (i >= KTOP) continue;
        float4 bi = g_boxes[b * KTOP + i];
        float ai = (bi.z - bi.x) * (bi.w - bi.y);
        unsigned long long bits = 0;
        for (int k = 0; k < 64; k++) {
            int jg = j0 + k;
            if (jg > i && jg < KTOP && iou_gt(bi, ai, cbx[k], car[k])) bits |= (1ull << k);
        }
        g_mask[rowbase + cb] = bits;
    }
}

// ---------------- Fallback B: full serial scan (gated) ----------------
__device__ __forceinline__ void issue_row94(const unsigned long long* src_row,
                                            unsigned dst_smem, int lane) {
    asm volatile("cp.async.ca.shared.global [%0], [%1], 16;\n"
                 :: "r"(dst_smem + lane * 16), "l"((const char*)src_row + lane * 16));
    if (lane < 15)
        asm volatile("cp.async.ca.shared.global [%0], [%1], 16;\n"
                     :: "r"(dst_smem + 512 + lane * 16),
                        "l"((const char*)src_row + 512 + lane * 16));
}

__global__ void k_scan_full() {
    if (g_need == 0) return;
    int b = blockIdx.x;
    int lane = threadIdx.x;
    __shared__ __align__(16) unsigned long long ring[8][WORDS];
    __shared__ unsigned long long removed[WORDS];
    removed[lane] = 0; removed[lane + 32] = 0;
    if (lane < WORDS - 64) removed[lane + 64] = 0;
    __syncwarp();

    const unsigned long long* maskb = g_mask + (size_t)b * KTOP * WORDS;
    unsigned ring_base = (unsigned)__cvta_generic_to_shared(&ring[0][0]);
    for (int p = 0; p < 7; p++) {
        issue_row94(maskb + (size_t)p * WORDS, ring_base + (p & 7) * (WORDS * 8), lane);
        asm volatile("cp.async.commit_group;\n");
    }
    unsigned long long cur = 0;
    int kept = 0;
    for (int i = 0; i < KTOP; i++) {
        int r = i + 7;
        if (r < KTOP)
            issue_row94(maskb + (size_t)r * WORDS, ring_base + (r & 7) * (WORDS * 8), lane);
        asm volatile("cp.async.commit_group;\n");
        asm volatile("cp.async.wait_group 7;\n");
        int w = i >> 6;
        if ((i & 63) == 0 && i) { __syncwarp(); cur = removed[w]; }
        if (!((cur >> (i & 63)) & 1ull)) {
            if (lane == 0) g_keep[b * OUTN + kept] = i;
            kept++;
            if (kept == OUTN) break;
            __syncwarp();
            const unsigned long long* row = ring[i & 7];
            cur |= row[w];
            removed[lane]      |= row[lane];
            removed[lane + 32] |= row[lane + 32];
            if (lane < WORDS - 64) removed[lane + 64] |= row[lane + 64];
        }
    }
    asm volatile("cp.async.wait_group 0;\n");
    __syncwarp();
    if (lane == 0) g_kept[b] = kept;
}

// ---------------- K7: write output (zero-padded) ----------------
__global__ void k_out(float4* __restrict__ out) {
    int t = blockIdx.x * blockDim.x + threadIdx.x;
    if (t >= BATCH * OUTN) return;
    int b = t / OUTN, r = t % OUTN;
    float4 v = make_float4(0, 0, 0, 0);
    if (r < g_kept[b]) v = g_boxes[b * KTOP + g_keep[b * OUTN + r]];
    out[t] = v;
}

// ---------------- launch ----------------
extern "C" void kernel_launch(void* const* d_in, const int* in_sizes, int n_in,
                              void* d_out, int out_size) {
    const float* scores  = (const float*)d_in[0];
    const float* deltas  = (const float*)d_in[1];
    const float* anchors = (const float*)d_in[2];
    int N = in_sizes[0] / (BATCH * 2);

    k_zero<<<64, 256>>>();
    k_hist<<<dim3(128, BATCH), 256>>>(scores, N);
    k_select<<<BATCH, 1024>>>();
    k_gather<<<dim3(128, BATCH), 256>>>(scores, N);
    k_rank<<<dim3(12, BATCH), 512>>>(deltas, anchors, N);
    k_maskC<<<dim3(WORDS_C, WORDS_C, BATCH), 64>>>();
    k_scanC<<<BATCH, 32>>>();
    k_mask_full<<<1024, 64>>>();   // no-op unless g_need
    k_scan_full<<<BATCH, 32>>>();  // no-op unless g_need
    k_out<<<16, 256>>>((float4*)d_out);
}